// round 6
// baseline (speedup 1.0000x reference)
#include <cuda_runtime.h>
#include <cstdint>

using ull = unsigned long long;
#define NROW 1024
#define NDIM 256
#define ROWS 4          // rows per CTA (2 f32x2 pairs)
#define ICH  32         // i-lanes per CTA (covers i and i^128 -> 64 outputs)
#define JG   8          // j-interleave groups (one per warp)

__device__ __forceinline__ void fma2(ull& d, ull a, ull b) {
    asm("fma.rn.f32x2 %0, %1, %2, %0;" : "+l"(d) : "l"(a), "l"(b));
}
__device__ __forceinline__ ull mul2(ull a, ull b) {
    ull r; asm("mul.rn.f32x2 %0, %1, %2;" : "=l"(r) : "l"(a), "l"(b));
    return r;
}
// suffix-parity mask: bit p of Uof(j) = parity of bits of j strictly above p.
// XOR-linear: Uof(a^b) = Uof(a)^Uof(b).  Uof(128)=127, bit7 always 0.
__host__ __device__ constexpr unsigned Uof(unsigned j) {
    unsigned v = j >> 1; v ^= v >> 1; v ^= v >> 2; v ^= v >> 4;
    return v & 255u;
}

__global__ void __launch_bounds__(256, 4)   // cap 64 regs -> 4 CTAs/SM
clifford_kernel(const float* __restrict__ A, const float* __restrict__ B,
                float* __restrict__ out) {
    __shared__ union SmemU {
        struct { float4 As[NDIM]; float4 Bs[NDIM]; } t;   // 8KB tiles
        ull stage[12][JG][ICH];                            // 24KB staging
    } sm;

    const unsigned tid = threadIdx.x;
    const unsigned gb  = blockIdx.x >> 2;   // row-group 0..255
    const unsigned ic  = blockIdx.x & 3;    // i-chunk   0..3 (i in [0,128))
    const unsigned rowBase = gb * ROWS;
    const unsigned ibase   = ic * ICH;

    // ---- fill: thread tid stages component j = tid for 4 rows ----
    {
        const unsigned j = tid;
        const float sg = (__popc(j & Uof(j)) & 1) ? -1.0f : 1.0f;
        float av[4], bv[4];
        #pragma unroll
        for (int r = 0; r < 4; ++r) {
            av[r] = A[(size_t)(rowBase + r) * NDIM + j] * sg;
            bv[r] = B[(size_t)(rowBase + r) * NDIM + j];
        }
        sm.t.As[j] = make_float4(av[0], av[1], av[2], av[3]);  // pairs (r0,r1),(r2,r3)
        sm.t.Bs[j] = make_float4(bv[0], bv[1], bv[2], bv[3]);
    }
    __syncthreads();

    const unsigned il = tid & 31;
    const unsigned jg = tid >> 5;
    const unsigned i  = ibase + il;         // i < 128; second output is i^128

    // hoisted per-thread constants
    const unsigned xbase  = i ^ jg;
    const unsigned ph     = (unsigned)(__popc(i & Uof(jg)) & 1) << 31;
    const unsigned sgb1   = 0x3f800000u ^ ph;                          // for output i
    const unsigned sgflip = (unsigned)(__popc(i) & 1) << 31;           // sgb2 = sgb1 ^ sgflip
    const unsigned g1     = jg & ~i;        // low part of (j & ~i), low7-safe
    const unsigned g2     = i & jg;         // low part of (i & j)
    const unsigned s0     = i & ~jg & 127u; // low part of (i & ~j)

    ull acc[12];                            // [prod*4 + ihalf*2 + pair]
    #pragma unroll
    for (int q = 0; q < 12; ++q) acc[q] = 0ull;

    const ulonglong2* __restrict__ Asp = reinterpret_cast<const ulonglong2*>(&sm.t.As[0]);
    const ulonglong2* __restrict__ Bsp = reinterpret_cast<const ulonglong2*>(&sm.t.Bs[0]);

    #pragma unroll
    for (unsigned m = 0; m < 32; ++m) {
        const unsigned jh = 8u * m;              // compile-time
        const unsigned jl = jh & 127u;           // compile-time
        const bool     h  = (jh & 128u) != 0u;   // compile-time
        const unsigned cU = Uof(jh);             // compile-time

        const unsigned j  = jh | jg;
        const unsigned x  = xbase ^ jh;

        const unsigned pc  = ((unsigned)__popc(i & cU) & 1u) << 31;
        const unsigned sg1 = sgb1 ^ pc;
        const unsigned sg2 = sg1 ^ sgflip;
        const ull sg1_64 = ((ull)sg1 << 32) | sg1;
        const ull sg2_64 = ((ull)sg2 << 32) | sg2;

        const bool W = (((jl & ~i) | g1) == 0u);     // j subset of i (low 7)
        const bool D = (((i & jl) | g2) == 0u);      // disjoint (low 7)
        const bool S = ((s0 & (~jl & 127u)) == 0u);  // i subset of j (low 7)

        const bool pw1 = (!h) && W;      // wedge for output i   (needs j7==0)
        const bool pw2 = W;              // wedge for output i^128 at j^128
        const bool pi1 = D | S;          // inner for output i
        const bool pi2 = h ? D : S;      // inner for output i^128 at j^128

        const ulonglong2 a1 = Asp[j];          // broadcast
        const ulonglong2 a2 = Asp[j ^ 128u];   // broadcast
        const ulonglong2 b  = Bsp[x];          // conflict-free gather, shared by both outputs

        // output i (terms j)
        ull t;
        t = mul2(a1.x, b.x);
        fma2(acc[0], t, sg1_64); if (pw1) fma2(acc[4], t, sg1_64); if (pi1) fma2(acc[8],  t, sg1_64);
        t = mul2(a1.y, b.y);
        fma2(acc[1], t, sg1_64); if (pw1) fma2(acc[5], t, sg1_64); if (pi1) fma2(acc[9],  t, sg1_64);
        // output i^128 (terms j^128), reusing b
        t = mul2(a2.x, b.x);
        fma2(acc[2], t, sg2_64); if (pw2) fma2(acc[6], t, sg2_64); if (pi2) fma2(acc[10], t, sg2_64);
        t = mul2(a2.y, b.y);
        fma2(acc[3], t, sg2_64); if (pw2) fma2(acc[7], t, sg2_64); if (pi2) fma2(acc[11], t, sg2_64);
    }

    // ---- deterministic cross-warp reduction over the 8 j-groups ----
    __syncthreads();                 // tiles fully consumed before overwrite
    #pragma unroll
    for (int q = 0; q < 12; ++q)
        sm.stage[q][jg][il] = acc[q];
    __syncthreads();

    {
        const unsigned qh0 = (tid >> 5) * 3;        // 3 outputs per thread
        #pragma unroll
        for (int k = 0; k < 3; ++k) {
            const unsigned qh   = qh0 + k;          // 0..23 = prod*8 + ihalf*4 + row
            const unsigned prod = qh >> 3;
            const unsigned rem  = qh & 7;
            const unsigned ih   = rem >> 2;         // 0: i, 1: i^128
            const unsigned r    = rem & 3;          // row 0..3
            const unsigned q    = prod * 4 + ih * 2 + (r >> 1);
            const unsigned hf   = r & 1;
            const float* sp = reinterpret_cast<const float*>(&sm.stage[q][0][0]);
            float s = 0.0f;
            #pragma unroll
            for (int w = 0; w < 8; ++w)
                s += sp[(w * ICH + il) * 2 + hf];
            out[(size_t)prod * (NROW * NDIM)
                + (size_t)(rowBase + r) * NDIM
                + ih * 128u + ibase + il] = s;
        }
    }
}

extern "C" void kernel_launch(void* const* d_in, const int* in_sizes, int n_in,
                              void* d_out, int out_size) {
    const float* A = (const float*)d_in[0];
    const float* B = (const float*)d_in[1];
    float* out = (float*)d_out;
    // 1024 rows / 4 rows-per-CTA = 256 row-groups; x 4 i-chunks = 1024 CTAs
    clifford_kernel<<<1024, 256>>>(A, B, out);
}

// round 7
// speedup vs baseline: 2.4223x; 2.4223x over previous
#include <cuda_runtime.h>
#include <cstdint>

using ull = unsigned long long;
#define NROW 1024
#define NDIM 256
#define ROWS 4          // rows per CTA (2 f32x2 pairs)
#define ICH  32         // i-lanes per CTA (covers i and i^128 -> 64 outputs)
#define JG   8          // j-interleave groups (one per warp)

__device__ __forceinline__ void fma2(ull& d, ull a, ull b) {
    asm("fma.rn.f32x2 %0, %1, %2, %0;" : "+l"(d) : "l"(a), "l"(b));
}
__device__ __forceinline__ ull mul2(ull a, ull b) {
    ull r; asm("mul.rn.f32x2 %0, %1, %2;" : "=l"(r) : "l"(a), "l"(b));
    return r;
}
// suffix-parity mask: bit p of Uof(j) = parity of bits of j strictly above p.
// XOR-linear: Uof(a^b) = Uof(a)^Uof(b).  Uof(128)=127, bit7 always 0.
__host__ __device__ constexpr unsigned Uof(unsigned j) {
    unsigned v = j >> 1; v ^= v >> 1; v ^= v >> 2; v ^= v >> 4;
    return v & 255u;
}

__global__ void __launch_bounds__(256, 3)   // 85-reg ceiling: loose backstop, no spills
clifford_kernel(const float* __restrict__ A, const float* __restrict__ B,
                float* __restrict__ out) {
    __shared__ union SmemU {
        struct { float4 As[NDIM]; float4 Bs[NDIM]; } t;   // 8KB tiles
        ull stage[12][JG][ICH];                            // 24KB staging
    } sm;

    const unsigned tid = threadIdx.x;
    const unsigned gb  = blockIdx.x >> 2;   // row-group 0..255
    const unsigned ic  = blockIdx.x & 3;    // i-chunk   0..3 (i in [0,128))
    const unsigned rowBase = gb * ROWS;
    const unsigned ibase   = ic * ICH;

    // ---- fill: thread tid stages component j = tid for 4 rows ----
    {
        const unsigned j = tid;
        const float sg = (__popc(j & Uof(j)) & 1) ? -1.0f : 1.0f;
        float av[4], bv[4];
        #pragma unroll
        for (int r = 0; r < 4; ++r) {
            av[r] = A[(size_t)(rowBase + r) * NDIM + j] * sg;
            bv[r] = B[(size_t)(rowBase + r) * NDIM + j];
        }
        sm.t.As[j] = make_float4(av[0], av[1], av[2], av[3]);  // pairs (r0,r1),(r2,r3)
        sm.t.Bs[j] = make_float4(bv[0], bv[1], bv[2], bv[3]);
    }
    __syncthreads();

    const unsigned il = tid & 31;
    const unsigned jg = tid >> 5;
    const unsigned i  = ibase + il;         // i < 128; second output is i^128

    // hoisted per-thread constants
    const unsigned xbase  = i ^ jg;
    const unsigned ph     = (unsigned)(__popc(i & Uof(jg)) & 1) << 31;
    const unsigned sgb1   = 0x3f800000u ^ ph;                          // for output i
    const unsigned sgflip = (unsigned)(__popc(i) & 1) << 31;           // sgb2 = sgb1 ^ sgflip
    const unsigned noti   = (~i) & 127u;

    ull acc[12];                            // [prod*4 + ihalf*2 + pair]
    #pragma unroll
    for (int q = 0; q < 12; ++q) acc[q] = 0ull;

    const ulonglong2* __restrict__ Asp = reinterpret_cast<const ulonglong2*>(&sm.t.As[0]);
    const ulonglong2* __restrict__ Bsp = reinterpret_cast<const ulonglong2*>(&sm.t.Bs[0]);

    // j = 64*t + 8*u + jg ; walk t outer (runtime, no unroll) to cap the
    // pipelining window, u inner (compile-time constants).
    #pragma unroll 1
    for (unsigned t = 0; t < 4; ++t) {
        const unsigned jo  = t << 6;                    // 0,64,128,192
        // Uof(jo) runtime (XOR-linear split of the sign)
        unsigned v = jo >> 1; v ^= v >> 1; v ^= v >> 2; v ^= v >> 4;
        const unsigned cUo   = v & 255u;
        const unsigned pco   = ((unsigned)__popc(i & cUo) & 1u) << 31;
        const unsigned sgb1o = sgb1 ^ pco;              // per-outer sign base (output i)
        const unsigned xo    = xbase ^ jo;
        const unsigned jol   = jo & 127u;               // 0 or 64
        const bool     hbit  = (jo & 128u) != 0u;       // j7 for this outer block
        // per-outer hoisted mask pieces (low-7 conditions)
        const unsigned joW = jol & noti;                // part of (j & ~i)
        const unsigned joD = i & jol;                   // part of (i & j)
        const unsigned sio = i & (~jol) & 127u;         // part of (i & ~j)

        #pragma unroll
        for (unsigned u = 0; u < 8; ++u) {
            const unsigned ju8 = 8u * u;                 // compile-time
            const unsigned cUu = Uof(ju8);               // compile-time
            const unsigned ju  = ju8 | jg;               // low-6 of j
            const unsigned j   = jo | ju;
            const unsigned x   = xo ^ ju8;

            const unsigned pcu = ((unsigned)__popc(i & cUu) & 1u) << 31;
            const unsigned sg1 = sgb1o ^ pcu;
            const unsigned sg2 = sg1 ^ sgflip;
            const ull sg1_64 = ((ull)sg1 << 32) | sg1;
            const ull sg2_64 = ((ull)sg2 << 32) | sg2;

            const bool W = ((joW | (ju & noti)) == 0u);   // j subset of i (low 7)
            const bool D = ((joD | (i & ju))   == 0u);    // disjoint (low 7)
            const bool S = ((sio & ~ju)        == 0u);    // i subset of j (low 7)

            const bool pw1 = (!hbit) && W;   // wedge, output i (needs j7==0)
            const bool pw2 = W;              // wedge, output i^128 at j^128
            const bool pi1 = D | S;          // inner, output i
            const bool pi2 = hbit ? D : S;   // inner, output i^128 at j^128

            const ulonglong2 a1 = Asp[j];          // broadcast
            const ulonglong2 a2 = Asp[j ^ 128u];   // broadcast
            const ulonglong2 b  = Bsp[x];          // conflict-free gather, shared

            ull tt;
            tt = mul2(a1.x, b.x);
            fma2(acc[0], tt, sg1_64); if (pw1) fma2(acc[4], tt, sg1_64); if (pi1) fma2(acc[8],  tt, sg1_64);
            tt = mul2(a1.y, b.y);
            fma2(acc[1], tt, sg1_64); if (pw1) fma2(acc[5], tt, sg1_64); if (pi1) fma2(acc[9],  tt, sg1_64);
            tt = mul2(a2.x, b.x);
            fma2(acc[2], tt, sg2_64); if (pw2) fma2(acc[6], tt, sg2_64); if (pi2) fma2(acc[10], tt, sg2_64);
            tt = mul2(a2.y, b.y);
            fma2(acc[3], tt, sg2_64); if (pw2) fma2(acc[7], tt, sg2_64); if (pi2) fma2(acc[11], tt, sg2_64);
        }
    }

    // ---- deterministic cross-warp reduction over the 8 j-groups ----
    __syncthreads();                 // tiles fully consumed before overwrite
    #pragma unroll
    for (int q = 0; q < 12; ++q)
        sm.stage[q][jg][il] = acc[q];
    __syncthreads();

    {
        const unsigned qh0 = (tid >> 5) * 3;        // 3 outputs per thread
        #pragma unroll
        for (int k = 0; k < 3; ++k) {
            const unsigned qh   = qh0 + k;          // 0..23 = prod*8 + ihalf*4 + row
            const unsigned prod = qh >> 3;
            const unsigned rem  = qh & 7;
            const unsigned ih   = rem >> 2;         // 0: i, 1: i^128
            const unsigned r    = rem & 3;          // row 0..3
            const unsigned q    = prod * 4 + ih * 2 + (r >> 1);
            const unsigned hf   = r & 1;
            const float* sp = reinterpret_cast<const float*>(&sm.stage[q][0][0]);
            float s = 0.0f;
            #pragma unroll
            for (int w = 0; w < 8; ++w)
                s += sp[(w * ICH + il) * 2 + hf];
            out[(size_t)prod * (NROW * NDIM)
                + (size_t)(rowBase + r) * NDIM
                + ih * 128u + ibase + il] = s;
        }
    }
}

extern "C" void kernel_launch(void* const* d_in, const int* in_sizes, int n_in,
                              void* d_out, int out_size) {
    const float* A = (const float*)d_in[0];
    const float* B = (const float*)d_in[1];
    float* out = (float*)d_out;
    // 1024 rows / 4 rows-per-CTA = 256 row-groups; x 4 i-chunks = 1024 CTAs
    clifford_kernel<<<1024, 256>>>(A, B, out);
}

// round 8
// speedup vs baseline: 3.8556x; 1.5917x over previous
#include <cuda_runtime.h>
#include <cstdint>

using ull = unsigned long long;
#define NROW 1024
#define NDIM 256
#define ROWS 4          // rows per CTA (2 f32x2 pairs)
#define ICH  32         // i-lanes per CTA (covers i and i^128 -> 64 outputs)
#define JG   8          // j-interleave groups (one per warp)

__device__ __forceinline__ void fma2(ull& d, ull a, ull b) {
    asm("fma.rn.f32x2 %0, %1, %2, %0;" : "+l"(d) : "l"(a), "l"(b));
}
__device__ __forceinline__ ull mul2(ull a, ull b) {
    ull r; asm("mul.rn.f32x2 %0, %1, %2;" : "=l"(r) : "l"(a), "l"(b));
    return r;
}
// suffix-parity mask: bit p of Uof(j) = parity of bits of j strictly above p.
__host__ __device__ constexpr unsigned Uof(unsigned j) {
    unsigned v = j >> 1; v ^= v >> 1; v ^= v >> 2; v ^= v >> 4;
    return v & 255u;
}
// indicator words over 5-bit m: bit m set iff condition on m holds
__device__ __forceinline__ unsigned subsetWord(unsigned M) {   // m subset of M
    const unsigned magic[5] = {0xAAAAAAAAu, 0xCCCCCCCCu, 0xF0F0F0F0u,
                               0xFF00FF00u, 0xFFFF0000u};
    unsigned w = 0xFFFFFFFFu;
    #pragma unroll
    for (int b = 0; b < 5; ++b)
        if (!((M >> b) & 1u)) w &= ~magic[b];
    return w;
}
__device__ __forceinline__ unsigned supersetWord(unsigned M) { // m superset of M
    const unsigned magic[5] = {0xAAAAAAAAu, 0xCCCCCCCCu, 0xF0F0F0F0u,
                               0xFF00FF00u, 0xFFFF0000u};
    unsigned w = 0xFFFFFFFFu;
    #pragma unroll
    for (int b = 0; b < 5; ++b)
        if ((M >> b) & 1u) w &= magic[b];
    return w;
}

__global__ void __launch_bounds__(256)      // NO min-blocks cap: let regs settle
clifford_kernel(const float* __restrict__ A, const float* __restrict__ B,
                float* __restrict__ out) {
    __shared__ union SmemU {
        struct { float4 As[NDIM]; float4 Bs[NDIM]; } t;   // 8KB tiles
        ull stage[12][JG][ICH];                            // 24KB staging
    } sm;

    const unsigned tid = threadIdx.x;
    const unsigned gb  = blockIdx.x >> 2;   // row-group 0..255
    const unsigned ic  = blockIdx.x & 3;    // i-chunk   0..3 (i in [0,128))
    const unsigned rowBase = gb * ROWS;
    const unsigned ibase   = ic * ICH;

    // ---- fill: thread tid stages component j = tid for 4 rows ----
    {
        const unsigned j = tid;
        const float sg = (__popc(j & Uof(j)) & 1) ? -1.0f : 1.0f;
        float av[4], bv[4];
        #pragma unroll
        for (int r = 0; r < 4; ++r) {
            av[r] = A[(size_t)(rowBase + r) * NDIM + j] * sg;
            bv[r] = B[(size_t)(rowBase + r) * NDIM + j];
        }
        sm.t.As[j] = make_float4(av[0], av[1], av[2], av[3]);  // pairs (r0,r1),(r2,r3)
        sm.t.Bs[j] = make_float4(bv[0], bv[1], bv[2], bv[3]);
    }
    __syncthreads();

    const unsigned il = tid & 31;
    const unsigned jg = tid >> 5;
    const unsigned i  = ibase + il;         // i < 128; second output is i^128
    const unsigned Mh = i >> 3;             // 0..15
    const unsigned il3 = i & 7u;

    // hoisted per-thread sign pieces
    const unsigned xbase  = i ^ jg;
    const unsigned ph     = (unsigned)(__popc(i & Uof(jg)) & 1) << 31;
    const unsigned sgb1   = 0x3f800000u ^ ph;                   // output i
    const unsigned sgflip = (unsigned)(__popc(i) & 1) << 31;    // sg2 = sg1 ^ sgflip

    // ---- sign indicator word: bit m = parity(i & U(8m)) (XOR-linear in m) ----
    unsigned Ws = 0;
    {
        const unsigned magic[5] = {0xAAAAAAAAu, 0xCCCCCCCCu, 0xF0F0F0F0u,
                                   0xFF00FF00u, 0xFFFF0000u};
        #pragma unroll
        for (int b = 0; b < 5; ++b)
            if (__popc(i & ((8u << b) - 1u)) & 1) Ws ^= magic[b];
    }

    // ---- predicate indicator words over m (j = 8m|jg, pair j^128) ----
    const bool condW = ((jg & ~i & 7u) == 0u);   // jg subset of i (low 3)
    const bool condD = ((i & jg) == 0u);         // low-3 disjoint
    const bool condS = ((il3 & ~jg & 7u) == 0u); // i low-3 subset of jg
    const unsigned subRep = subsetWord(Mh | 16u);            // (m&15) subset Mh
    const unsigned dRep   = subsetWord((~Mh & 15u) | 16u);   // (m&15) disjoint Mh
    const unsigned supRep = supersetWord(Mh);                // (m&15) superset Mh
    const unsigned Wwe2  = condW ? subRep : 0u;              // wedge, output i^128
    const unsigned Wwe1  = Wwe2 & 0xFFFFu;                   // wedge, output i (j7==0)
    const unsigned Winn1 = (condD ? dRep : 0u) | (condS ? supRep : 0u);
    const unsigned Winn2 = (condD ? (dRep & 0xFFFF0000u) : 0u)
                         | (condS ? (supRep & 0xFFFFu) : 0u);

    ull acc[12];                            // [prod*4 + ihalf*2 + pair]
    #pragma unroll
    for (int q = 0; q < 12; ++q) acc[q] = 0ull;

    const ulonglong2* __restrict__ Asp = reinterpret_cast<const ulonglong2*>(&sm.t.As[0]);
    const ulonglong2* __restrict__ Bsp = reinterpret_cast<const ulonglong2*>(&sm.t.Bs[0]);

    #pragma unroll 8
    for (unsigned m = 0; m < 32; ++m) {
        const unsigned j  = (m << 3) | jg;
        const unsigned x  = xbase ^ (m << 3);

        const unsigned sb  = (Ws << (31u - m)) & 0x80000000u;  // sign bit for this m
        const unsigned sg1 = sgb1 ^ sb;
        const unsigned sg2 = sg1 ^ sgflip;
        const ull sg1_64 = ((ull)sg1 << 32) | sg1;
        const ull sg2_64 = ((ull)sg2 << 32) | sg2;

        const bool pw1 = (Wwe1  >> m) & 1u;
        const bool pw2 = (Wwe2  >> m) & 1u;
        const bool pi1 = (Winn1 >> m) & 1u;
        const bool pi2 = (Winn2 >> m) & 1u;

        const ulonglong2 a1 = Asp[j];          // broadcast
        const ulonglong2 a2 = Asp[j ^ 128u];   // broadcast
        const ulonglong2 b  = Bsp[x];          // conflict-free gather, shared

        ull t;
        t = mul2(a1.x, b.x);
        fma2(acc[0], t, sg1_64); if (pw1) fma2(acc[4], t, sg1_64); if (pi1) fma2(acc[8],  t, sg1_64);
        t = mul2(a1.y, b.y);
        fma2(acc[1], t, sg1_64); if (pw1) fma2(acc[5], t, sg1_64); if (pi1) fma2(acc[9],  t, sg1_64);
        t = mul2(a2.x, b.x);
        fma2(acc[2], t, sg2_64); if (pw2) fma2(acc[6], t, sg2_64); if (pi2) fma2(acc[10], t, sg2_64);
        t = mul2(a2.y, b.y);
        fma2(acc[3], t, sg2_64); if (pw2) fma2(acc[7], t, sg2_64); if (pi2) fma2(acc[11], t, sg2_64);
    }

    // ---- deterministic cross-warp reduction over the 8 j-groups ----
    __syncthreads();                 // tiles fully consumed before overwrite
    #pragma unroll
    for (int q = 0; q < 12; ++q)
        sm.stage[q][jg][il] = acc[q];
    __syncthreads();

    {
        const unsigned qh0 = (tid >> 5) * 3;        // 3 outputs per thread
        #pragma unroll
        for (int k = 0; k < 3; ++k) {
            const unsigned qh   = qh0 + k;          // 0..23 = prod*8 + ihalf*4 + row
            const unsigned prod = qh >> 3;
            const unsigned rem  = qh & 7;
            const unsigned ih   = rem >> 2;         // 0: i, 1: i^128
            const unsigned r    = rem & 3;          // row 0..3
            const unsigned q    = prod * 4 + ih * 2 + (r >> 1);
            const unsigned hf   = r & 1;
            const float* sp = reinterpret_cast<const float*>(&sm.stage[q][0][0]);
            float s = 0.0f;
            #pragma unroll
            for (int w = 0; w < 8; ++w)
                s += sp[(w * ICH + il) * 2 + hf];
            out[(size_t)prod * (NROW * NDIM)
                + (size_t)(rowBase + r) * NDIM
                + ih * 128u + ibase + il] = s;
        }
    }
}

extern "C" void kernel_launch(void* const* d_in, const int* in_sizes, int n_in,
                              void* d_out, int out_size) {
    const float* A = (const float*)d_in[0];
    const float* B = (const float*)d_in[1];
    float* out = (float*)d_out;
    // 1024 rows / 4 rows-per-CTA = 256 row-groups; x 4 i-chunks = 1024 CTAs
    clifford_kernel<<<1024, 256>>>(A, B, out);
}